// round 4
// baseline (speedup 1.0000x reference)
#include <cuda_runtime.h>
#include <cstdint>

// AttentionDownsampler v4: single coalesced float4 read + leader handshake.
// pixel_dot[b,y,x] = sum_c hr[b,c,y,x]*aw[c] is channel-separable, so CTAs
// split channels. CTA = (slab=b*16+ph, cg of 16 channels), 24 groups/slab.
//   Phase 1: 7 LDG.128/thread stage 16ch x 7rows x 112 cols into smem,
//            smem pass computes this group's pixel-dot partial, publish.
//   Leader (cg==0): waits 24 arrivals, sums partials, softmax for 16 patches,
//            publishes attn[784]; followers spin on flag, pull attn.
//   Phase 2: per-(channel,pw) weighted sum from smem tile. hr read ONCE.

#define DIM     384
#define KS      7
#define NP      49
#define HW      112
#define PLANE   (HW * HW)
#define FN      16
#define NSLAB   128               // (b, ph)
#define NCG     24                // channel groups per slab
#define CPG     16                // channels per group
#define SLABPIX 784               // 7*112
#define THREADS 448               // (x4:28, cc:16)
#define DROP_P  0.2f

#define TILE_F  (CPG * SLABPIX)   // 12544 floats
#define SMEM_F  (TILE_F + SLABPIX + SLABPIX + CPG)
#define SMEM_B  (SMEM_F * 4)      // 56512 B -> 3 CTAs/SM

__device__ float g_part[(size_t)NSLAB * NCG * SLABPIX];
__device__ float g_attn[(size_t)NSLAB * SLABPIX];
__device__ int   g_cnt[NSLAB];
__device__ int   g_done[NSLAB];

__global__ void zero_flags_kernel()
{
    if (threadIdx.x < NSLAB) {
        g_cnt[threadIdx.x]  = 0;
        g_done[threadIdx.x] = 0;
    }
}

__global__ void __launch_bounds__(THREADS, 3)
attn_downsampler_kernel(const float* __restrict__ hr,
                        const float* __restrict__ du,
                        const float* __restrict__ aw,
                        const float* __restrict__ ab,
                        const float* __restrict__ wmat,
                        const float* __restrict__ bmat,
                        float* __restrict__ out)
{
    extern __shared__ float smem[];
    float* tile   = smem;                    // [CPG][784]
    float* pd_s   = tile + TILE_F;           // [784]
    float* attn_s = pd_s + SLABPIX;          // [16][49]
    float* awsh   = attn_s + SLABPIX;        // [16]

    const int bid   = blockIdx.x;
    const int slab  = bid / NCG;
    const int cg    = bid - slab * NCG;
    const int ph    = slab & (FN - 1);
    const int b     = slab >> 4;
    const int cbase = cg * CPG;

    const int tid = threadIdx.x;
    const int x4  = tid % 28;                // float4 column 0..27
    const int cc  = tid / 28;                // channel 0..15

    if (tid < CPG) awsh[tid] = __ldg(aw + cbase + tid);

    // ---- phase 1: 7 x LDG.128, perfectly coalesced 448B rows ----
    const float4* gp = (const float4*)(hr
        + (size_t)(b * DIM + cbase + cc) * PLANE
        + (size_t)(ph * KS) * HW) + x4;
    float* ts = tile + cc * SLABPIX + x4 * 4;
    #pragma unroll
    for (int dy = 0; dy < KS; dy++) {
        float4 v = __ldg(gp + dy * 28);
        *(float4*)(ts + dy * HW) = v;
    }
    __syncthreads();

    // ---- pixel-dot partial (16-channel smem reduction), publish ----
    float* slot = g_part + ((size_t)slab * NCG + cg) * SLABPIX;
    for (int i = tid; i < SLABPIX; i += THREADS) {
        float s = 0.f;
        #pragma unroll
        for (int c2 = 0; c2 < CPG; c2++)
            s = fmaf(tile[c2 * SLABPIX + i], awsh[c2], s);
        pd_s[i] = s;
        slot[i] = s;
    }
    __threadfence();
    __syncthreads();
    if (tid == 0) atomicAdd(&g_cnt[slab], 1);

    if (cg == 0) {
        // ---- leader: gather partials, softmax, publish attn ----
        if (tid == 0) {
            while (atomicAdd(&g_cnt[slab], 0) < NCG) __nanosleep(64);
        }
        __syncthreads();
        __threadfence();
        for (int i = tid; i < SLABPIX; i += THREADS) {
            const float* pp = g_part + (size_t)slab * NCG * SLABPIX + i;
            float s = 0.f;
            #pragma unroll
            for (int k = 0; k < NCG; k++) s += pp[k * SLABPIX];
            pd_s[i] = s;
        }
        __syncthreads();

        {   // softmax: warp wid handles pw = wid, wid+14
            const int wid = tid >> 5, lane = tid & 31;
            const float abv = __ldg(ab);
            for (int pw = wid; pw < FN; pw += 14) {
                const float m = (__ldg(du + (b * FN + ph) * FN + pw) > DROP_P) ? 1.f : 0.f;
                const int p0 = lane, p1 = lane + 32;
                float v0 = -1e30f, v1 = -1e30f;
                if (p0 < NP) {
                    int dy = p0 / KS, dx = p0 - dy * KS;
                    v0 = (pd_s[dy * HW + pw * KS + dx] + abv) * m * __ldg(wmat + p0) + __ldg(bmat + p0);
                }
                if (p1 < NP) {
                    int dy = p1 / KS, dx = p1 - dy * KS;
                    v1 = (pd_s[dy * HW + pw * KS + dx] + abv) * m * __ldg(wmat + p1) + __ldg(bmat + p1);
                }
                float mx = fmaxf(v0, v1);
                #pragma unroll
                for (int o = 16; o; o >>= 1)
                    mx = fmaxf(mx, __shfl_xor_sync(0xffffffffu, mx, o));
                float e0 = (p0 < NP) ? __expf(v0 - mx) : 0.f;
                float e1 = (p1 < NP) ? __expf(v1 - mx) : 0.f;
                float ss = e0 + e1;
                #pragma unroll
                for (int o = 16; o; o >>= 1)
                    ss += __shfl_xor_sync(0xffffffffu, ss, o);
                const float inv = 1.f / ss;
                if (p0 < NP) attn_s[pw * NP + p0] = e0 * inv;
                if (p1 < NP) attn_s[pw * NP + p1] = e1 * inv;
            }
        }
        __syncthreads();
        for (int i = tid; i < SLABPIX; i += THREADS)
            g_attn[(size_t)slab * SLABPIX + i] = attn_s[i];
        __threadfence();
        __syncthreads();
        if (tid == 0) atomicExch(&g_done[slab], 1);
    } else {
        // ---- follower: wait for attn ----
        if (tid == 0) {
            while (atomicAdd(&g_done[slab], 0) == 0) __nanosleep(128);
        }
        __syncthreads();
        __threadfence();
        for (int i = tid; i < SLABPIX; i += THREADS)
            attn_s[i] = g_attn[(size_t)slab * SLABPIX + i];
        __syncthreads();
    }

    // ---- phase 2: epilogue, thread = (channel, pw) ----
    if (tid < CPG * FN) {
        const int lc = tid >> 4, pw = tid & 15;
        const float* tp = tile + lc * SLABPIX + pw * KS;
        const float* ap = attn_s + pw * NP;
        float acc = 0.f;
        #pragma unroll
        for (int dy = 0; dy < KS; dy++)
            #pragma unroll
            for (int dx = 0; dx < KS; dx++)
                acc = fmaf(tp[dy * HW + dx], ap[dy * KS + dx], acc);
        const int c = cbase + lc;
        out[((size_t)(b * DIM + c) * FN + ph) * FN + pw] = acc;
    }
}

extern "C" void kernel_launch(void* const* d_in, const int* in_sizes, int n_in,
                              void* d_out, int out_size)
{
    const float* hr   = (const float*)d_in[0];   // (8,384,112,112)
    // d_in[1] = guidance (unused)
    const float* du   = (const float*)d_in[2];   // (8,16,16,1)
    const float* aw   = (const float*)d_in[3];   // (384,)
    const float* ab   = (const float*)d_in[4];   // (1,)
    const float* wmat = (const float*)d_in[5];   // (7,7)
    const float* bmat = (const float*)d_in[6];   // (7,7)
    float* out = (float*)d_out;                  // (8,384,16,16)

    cudaFuncSetAttribute(attn_downsampler_kernel,
                         cudaFuncAttributeMaxDynamicSharedMemorySize, SMEM_B);

    zero_flags_kernel<<<1, 128>>>();
    attn_downsampler_kernel<<<NSLAB * NCG, THREADS, SMEM_B>>>(
        hr, du, aw, ab, wmat, bmat, out);
}

// round 5
// speedup vs baseline: 1.5612x; 1.5612x over previous
#include <cuda_runtime.h>
#include <cstdint>

// AttentionDownsampler v5: two streaming kernels, zero cross-CTA sync.
//  K1: pixel_dot[b,y,x] = sum_c hr*aw  (warp = 32 consecutive x -> 128B lines)
//      + in-CTA softmax for the slab's 16 patches -> g_attn.
//  K3: re-read hr (float4 rows) + weighted-sum epilogue using g_attn.
// Cost model: 2 x 154MB DRAM-bound streams, no handshake stalls.

#define DIM     384
#define KS      7
#define NP      49
#define HW      112
#define PLANE   (HW * HW)
#define FN      16
#define NSLAB   128               // (b, ph)
#define SLABPIX 784               // 7*112
#define DROP_P  0.2f

// ---- K3 geometry ----
#define NCG     24
#define CPG     16
#define T3      448               // (x4:28, cc:16)
#define TILE_F  (CPG * SLABPIX)   // 12544
#define SMEM3_F (TILE_F + SLABPIX)
#define SMEM3_B (SMEM3_F * 4)     // 53312 B -> 4 CTAs/SM

__device__ float g_attn[(size_t)NSLAB * SLABPIX];   // [slab][pw][49]

// ================= K1: pixel dot + softmax =================
__global__ void __launch_bounds__(SLABPIX, 1)
k1_dot_softmax(const float* __restrict__ hr,
               const float* __restrict__ du,
               const float* __restrict__ aw,
               const float* __restrict__ ab,
               const float* __restrict__ wmat,
               const float* __restrict__ bmat)
{
    __shared__ float awsh[DIM];
    __shared__ float pd_s[SLABPIX];

    const int slab = blockIdx.x;
    const int ph   = slab & (FN - 1);
    const int b    = slab >> 4;

    const int tid = threadIdx.x;          // pixel (dy, x): tid = dy*112 + x
    if (tid < DIM) awsh[tid] = __ldg(aw + tid);
    __syncthreads();

    // thread's pixel: row = ph*7 + dy, col = x
    const float* gp = hr + (size_t)b * DIM * PLANE + (size_t)(ph * KS) * HW + tid;

    float s = 0.f;
    #pragma unroll 8
    for (int c = 0; c < DIM; c++)
        s = fmaf(__ldg(gp + (size_t)c * PLANE), awsh[c], s);
    pd_s[tid] = s;
    __syncthreads();

    // softmax: warp wid (0..15) handles patch pw = wid
    const int wid = tid >> 5, lane = tid & 31;
    if (wid < FN) {
        const int pw = wid;
        const float m   = (__ldg(du + (b * FN + ph) * FN + pw) > DROP_P) ? 1.f : 0.f;
        const float abv = __ldg(ab);
        const int p0 = lane, p1 = lane + 32;
        float v0 = -1e30f, v1 = -1e30f;
        if (p0 < NP) {
            int dy = p0 / KS, dx = p0 - dy * KS;
            v0 = (pd_s[dy * HW + pw * KS + dx] + abv) * m * __ldg(wmat + p0) + __ldg(bmat + p0);
        }
        if (p1 < NP) {
            int dy = p1 / KS, dx = p1 - dy * KS;
            v1 = (pd_s[dy * HW + pw * KS + dx] + abv) * m * __ldg(wmat + p1) + __ldg(bmat + p1);
        }
        float mx = fmaxf(v0, v1);
        #pragma unroll
        for (int o = 16; o; o >>= 1)
            mx = fmaxf(mx, __shfl_xor_sync(0xffffffffu, mx, o));
        float e0 = (p0 < NP) ? __expf(v0 - mx) : 0.f;
        float e1 = (p1 < NP) ? __expf(v1 - mx) : 0.f;
        float ss = e0 + e1;
        #pragma unroll
        for (int o = 16; o; o >>= 1)
            ss += __shfl_xor_sync(0xffffffffu, ss, o);
        const float inv = 1.f / ss;
        float* dst = g_attn + (size_t)slab * SLABPIX + pw * NP;
        if (p0 < NP) dst[p0] = e0 * inv;
        if (p1 < NP) dst[p1] = e1 * inv;
    }
}

// ================= K3: epilogue =================
__global__ void __launch_bounds__(T3, 4)
k3_epilogue(const float* __restrict__ hr, float* __restrict__ out)
{
    extern __shared__ float smem[];
    float* tile   = smem;                 // [CPG][784]
    float* attn_s = tile + TILE_F;        // [16][49]

    const int bid   = blockIdx.x;
    const int slab  = bid / NCG;
    const int cg    = (NCG - 1) - (bid - slab * NCG);  // high channels first
    const int ph    = slab & (FN - 1);
    const int b     = slab >> 4;
    const int cbase = cg * CPG;

    const int tid = threadIdx.x;
    const int x4  = tid % 28;
    const int cc  = tid / 28;

    // pull this slab's attn (tiny, L2-hot: shared by 24 CTAs)
    for (int i = tid; i < SLABPIX; i += T3)
        attn_s[i] = __ldg(g_attn + (size_t)slab * SLABPIX + i);

    // stage 16ch x 7rows x 112 cols, 7 x LDG.128 per thread
    const float4* gp = (const float4*)(hr
        + (size_t)(b * DIM + cbase + cc) * PLANE
        + (size_t)(ph * KS) * HW) + x4;
    float* ts = tile + cc * SLABPIX + x4 * 4;
    #pragma unroll
    for (int dy = 0; dy < KS; dy++)
        *(float4*)(ts + dy * HW) = __ldg(gp + dy * 28);
    __syncthreads();

    // thread = (channel, pw): 49 LDS+FMA, conflict-free (7 coprime 32)
    if (tid < CPG * FN) {
        const int lc = tid >> 4, pw = tid & 15;
        const float* tp = tile + lc * SLABPIX + pw * KS;
        const float* ap = attn_s + pw * NP;
        float acc = 0.f;
        #pragma unroll
        for (int dy = 0; dy < KS; dy++)
            #pragma unroll
            for (int dx = 0; dx < KS; dx++)
                acc = fmaf(tp[dy * HW + dx], ap[dy * KS + dx], acc);
        out[((size_t)(b * DIM + cbase + lc) * FN + ph) * FN + pw] = acc;
    }
}

extern "C" void kernel_launch(void* const* d_in, const int* in_sizes, int n_in,
                              void* d_out, int out_size)
{
    const float* hr   = (const float*)d_in[0];   // (8,384,112,112)
    // d_in[1] = guidance (unused)
    const float* du   = (const float*)d_in[2];   // (8,16,16,1)
    const float* aw   = (const float*)d_in[3];   // (384,)
    const float* ab   = (const float*)d_in[4];   // (1,)
    const float* wmat = (const float*)d_in[5];   // (7,7)
    const float* bmat = (const float*)d_in[6];   // (7,7)
    float* out = (float*)d_out;                  // (8,384,16,16)

    cudaFuncSetAttribute(k3_epilogue,
                         cudaFuncAttributeMaxDynamicSharedMemorySize, SMEM3_B);

    k1_dot_softmax<<<NSLAB, SLABPIX>>>(hr, du, aw, ab, wmat, bmat);
    k3_epilogue<<<NSLAB * NCG, T3, SMEM3_B>>>(hr, out);
}

// round 6
// speedup vs baseline: 1.8569x; 1.1894x over previous
#include <cuda_runtime.h>
#include <cstdint>

// AttentionDownsampler v6: two streaming kernels, no cross-CTA sync, no staging.
//  K1: pixel_dot = sum_c hr*aw, half-slab CTAs (256), 2-acc unroll-16 c-loop,
//      in-CTA softmax for 8 patches -> g_attn.
//  K3: re-read hr as float4 rows; each thread keeps its 28 attn coefs in
//      registers and FMAs loads straight into 4 accumulators; combine via
//      smem atomicAdd into out[16ch][16pw]. No tile, no wide barrier tail.

#define DIM     384
#define KS      7
#define NP      49
#define HW      112
#define PLANE   (HW * HW)
#define FN      16
#define NSLAB   128               // (b, ph)
#define SLABPIX 784
#define DROP_P  0.2f

#define NCG     24
#define CPG     16
#define T3      448               // (x4:28, cc:16)

__device__ float g_attn[(size_t)NSLAB * SLABPIX];   // [slab][pw][49]

// ================= K1: pixel dot + softmax (half-slab CTAs) ==============
__global__ void __launch_bounds__(392, 2)
k1_dot_softmax(const float* __restrict__ hr,
               const float* __restrict__ du,
               const float* __restrict__ aw,
               const float* __restrict__ ab,
               const float* __restrict__ wmat,
               const float* __restrict__ bmat)
{
    __shared__ float awsh[DIM];
    __shared__ float pd_s[392];

    const int bid  = blockIdx.x;
    const int xh   = bid & 1;            // x half: columns [xh*56, xh*56+56)
    const int slab = bid >> 1;
    const int ph   = slab & (FN - 1);
    const int b    = slab >> 4;

    const int tid = threadIdx.x;         // tid = dy*56 + xl
    const int dy  = tid / 56;
    const int xl  = tid - dy * 56;

    if (tid < DIM) awsh[tid] = __ldg(aw + tid);
    __syncthreads();

    const float* gp = hr + (size_t)b * DIM * PLANE
                         + (size_t)(ph * KS + dy) * HW + xh * 56 + xl;

    float s0 = 0.f, s1 = 0.f;
    #pragma unroll 8
    for (int c = 0; c < DIM; c += 2) {
        s0 = fmaf(__ldg(gp + (size_t)c * PLANE),       awsh[c],     s0);
        s1 = fmaf(__ldg(gp + (size_t)(c + 1) * PLANE), awsh[c + 1], s1);
    }
    pd_s[tid] = s0 + s1;
    __syncthreads();

    // softmax: warp w (0..7) handles local patch pwl = w  (pw = xh*8 + w)
    const int wid = tid >> 5, lane = tid & 31;
    if (wid < 8) {
        const int pw = xh * 8 + wid;
        const float m   = (__ldg(du + (b * FN + ph) * FN + pw) > DROP_P) ? 1.f : 0.f;
        const float abv = __ldg(ab);
        const int p0 = lane, p1 = lane + 32;
        float v0 = -1e30f, v1 = -1e30f;
        if (p0 < NP) {
            int d = p0 / KS, e = p0 - d * KS;
            v0 = (pd_s[d * 56 + wid * KS + e] + abv) * m * __ldg(wmat + p0) + __ldg(bmat + p0);
        }
        if (p1 < NP) {
            int d = p1 / KS, e = p1 - d * KS;
            v1 = (pd_s[d * 56 + wid * KS + e] + abv) * m * __ldg(wmat + p1) + __ldg(bmat + p1);
        }
        float mx = fmaxf(v0, v1);
        #pragma unroll
        for (int o = 16; o; o >>= 1)
            mx = fmaxf(mx, __shfl_xor_sync(0xffffffffu, mx, o));
        float e0 = (p0 < NP) ? __expf(v0 - mx) : 0.f;
        float e1 = (p1 < NP) ? __expf(v1 - mx) : 0.f;
        float ss = e0 + e1;
        #pragma unroll
        for (int o = 16; o; o >>= 1)
            ss += __shfl_xor_sync(0xffffffffu, ss, o);
        const float inv = 1.f / ss;
        float* dst = g_attn + (size_t)slab * SLABPIX + pw * NP;
        if (p0 < NP) dst[p0] = e0 * inv;
        if (p1 < NP) dst[p1] = e1 * inv;
    }
}

// ================= K3: register-accumulate epilogue ======================
__global__ void __launch_bounds__(T3, 4)
k3_epilogue(const float* __restrict__ hr, float* __restrict__ out)
{
    __shared__ float attn_s[SLABPIX];
    __shared__ float out_s[CPG * FN];    // [ch][pw]

    const int bid   = blockIdx.x;
    const int slab  = bid / NCG;
    const int cg    = bid - slab * NCG;
    const int ph    = slab & (FN - 1);
    const int b     = slab >> 4;
    const int cbase = cg * CPG;

    const int tid = threadIdx.x;
    const int x4  = tid % 28;            // float4 column
    const int cc  = tid / 28;            // channel 0..15

    for (int i = tid; i < SLABPIX; i += T3)
        attn_s[i] = __ldg(g_attn + (size_t)slab * SLABPIX + i);
    if (tid < CPG * FN) out_s[tid] = 0.f;
    __syncthreads();

    // per-element patch mapping: x = 4*x4 + k -> (pw, dx)
    int pwk[4], cidx[4];
    #pragma unroll
    for (int k = 0; k < 4; k++) {
        const int x  = 4 * x4 + k;
        const int pw = x / KS;
        pwk[k]  = pw;
        cidx[k] = pw * NP + (x - pw * KS);
    }
    // hoist all 28 attn coefficients into registers
    float coef[4][KS];
    #pragma unroll
    for (int k = 0; k < 4; k++)
        #pragma unroll
        for (int d = 0; d < KS; d++)
            coef[k][d] = attn_s[cidx[k] + d * KS];

    // stream 7 float4 rows, FMA directly into 4 accumulators
    const float4* gp = (const float4*)(hr
        + (size_t)(b * DIM + cbase + cc) * PLANE
        + (size_t)(ph * KS) * HW) + x4;
    float acc[4] = {0.f, 0.f, 0.f, 0.f};
    #pragma unroll
    for (int d = 0; d < KS; d++) {
        float4 v = __ldg(gp + d * 28);
        acc[0] = fmaf(v.x, coef[0][d], acc[0]);
        acc[1] = fmaf(v.y, coef[1][d], acc[1]);
        acc[2] = fmaf(v.z, coef[2][d], acc[2]);
        acc[3] = fmaf(v.w, coef[3][d], acc[3]);
    }

    // combine the <=2 distinct pw groups of this thread into smem
    {
        int   cur = pwk[0];
        float a   = acc[0];
        #pragma unroll
        for (int k = 1; k < 4; k++) {
            if (pwk[k] == cur) a += acc[k];
            else { atomicAdd(&out_s[cc * FN + cur], a); cur = pwk[k]; a = acc[k]; }
        }
        atomicAdd(&out_s[cc * FN + cur], a);
    }
    __syncthreads();

    if (tid < CPG * FN) {
        const int lc = tid >> 4, pw = tid & 15;
        out[((size_t)(b * DIM + cbase + lc) * FN + ph) * FN + pw] = out_s[tid];
    }
}

extern "C" void kernel_launch(void* const* d_in, const int* in_sizes, int n_in,
                              void* d_out, int out_size)
{
    const float* hr   = (const float*)d_in[0];   // (8,384,112,112)
    // d_in[1] = guidance (unused)
    const float* du   = (const float*)d_in[2];   // (8,16,16,1)
    const float* aw   = (const float*)d_in[3];   // (384,)
    const float* ab   = (const float*)d_in[4];   // (1,)
    const float* wmat = (const float*)d_in[5];   // (7,7)
    const float* bmat = (const float*)d_in[6];   // (7,7)
    float* out = (float*)d_out;                  // (8,384,16,16)

    k1_dot_softmax<<<NSLAB * 2, 392>>>(hr, du, aw, ab, wmat, bmat);
    k3_epilogue<<<NSLAB * NCG, T3>>>(hr, out);
}